// round 2
// baseline (speedup 1.0000x reference)
#include <cuda_runtime.h>
#include <math.h>

// Problem constants (fixed by setup_inputs)
#define U      128     // hidden units
#define ZD     512     // 4*U gate width
#define NC     10      // classes
#define NF     3       // input features
#define TT     1000    // timesteps
#define BB     256     // batch
#define G      4       // batch elements per block
#define NBLK   (BB/G)  // 64 blocks
#define NTHR   256

#define R_ON_   0.05f
#define ALPHA_  0.001f
#define LN_EPS_ 1e-3f

// ---- packed f32x2 helpers (Blackwell FFMA2: 2x fp32 FMA throughput) ----
__device__ __forceinline__ unsigned long long pack2(float a, float b) {
    unsigned long long r;
    asm("mov.b64 %0, {%1, %2};" : "=l"(r) : "f"(a), "f"(b));
    return r;
}
__device__ __forceinline__ float2 unpack2(unsigned long long v) {
    float2 r;
    asm("mov.b64 {%0, %1}, %2;" : "=f"(r.x), "=f"(r.y) : "l"(v));
    return r;
}
__device__ __forceinline__ void fma2p(unsigned long long& acc,
                                      unsigned long long w,
                                      unsigned long long h) {
    asm("fma.rn.f32x2 %0, %1, %2, %0;" : "+l"(acc) : "l"(w), "l"(h));
}

__device__ __forceinline__ float sigmoidf_(float x) { return 1.0f / (1.0f + expf(-x)); }

struct __align__(16) Smem {
    float z[2][G][ZD];          // per-K-slab partial gate pre-activations
    float h0[G][U], c0[G][U];
    float h1[G][U], c1[G][U];
    float hn[G][U];             // layernormed h0
    float Wx0[NF][ZD];
    float b0[ZD], b1[ZD];
    float tau0[U], s0[U], tau1[U], s1[U], gm[U], bt[U];
    float Wfc[U * NC];
    float bfc[NC];
    float x[2][G][NF];          // double-buffered inputs
    float tm[2][G];             // double-buffered times
    float red_s[G][4], red_q[G][4];
    float mu[G], rs[G];
    float logits[G][NC];
};

// Accumulate one 64-row K-slab of  hin[G][U] @ W[U][ZD]  into acc (4 cols/thread).
__device__ __forceinline__ void mv_accum(const float* __restrict__ W,
                                         const float* __restrict__ hin,
                                         int ks, int col,
                                         unsigned long long acc[G][2]) {
    const int kbase = ks * 64;
    #pragma unroll 4
    for (int k = 0; k < 64; ++k) {
        const int kk = kbase + k;
        float4 w = *reinterpret_cast<const float4*>(W + (size_t)kk * ZD + col);
        unsigned long long w01 = pack2(w.x, w.y);
        unsigned long long w23 = pack2(w.z, w.w);
        #pragma unroll
        for (int g = 0; g < G; ++g) {
            float hv = hin[g * U + kk];
            unsigned long long h2 = pack2(hv, hv);
            fma2p(acc[g][0], w01, h2);
            fma2p(acc[g][1], w23, h2);
        }
    }
}

// PhasedLSTM gate + time-gate update for one (batch, unit).
__device__ __forceinline__ void plstm_gate(const float* __restrict__ z0,
                                           const float* __restrict__ z1,
                                           int u, float tcur, float tau, float s,
                                           float& h, float& c) {
    float zi = z0[u]         + z1[u];
    float zf = z0[u + 128]   + z1[u + 128];
    float zg = z0[u + 256]   + z1[u + 256];
    float zo = z0[u + 384]   + z1[u + 384];
    float ch = sigmoidf_(zf) * c + sigmoidf_(zi) * tanhf(zg);
    float hh = sigmoidf_(zo) * tanhf(ch);

    float d = tcur - s;
    float m = fmodf(d, tau);          // exact, matches lax.rem
    if (m < 0.0f) m += tau;           // python-style mod (sign of divisor)
    float phi = m / tau;
    float kgate;
    if (phi < 0.5f * R_ON_)      kgate = 2.0f * phi / R_ON_;
    else if (phi < R_ON_)        kgate = 2.0f - 2.0f * phi / R_ON_;
    else                         kgate = ALPHA_ * phi;

    h = kgate * hh + (1.0f - kgate) * h;
    c = kgate * ch + (1.0f - kgate) * c;
}

__global__ void __launch_bounds__(NTHR, 1)
plstm_kernel(const float* __restrict__ inputs, const float* __restrict__ times,
             const float* __restrict__ gWx0, const float* __restrict__ gWh0,
             const float* __restrict__ gb0,  const float* __restrict__ gtau0,
             const float* __restrict__ gs0,  const float* __restrict__ gWx1,
             const float* __restrict__ gWh1, const float* __restrict__ gb1,
             const float* __restrict__ gtau1,const float* __restrict__ gs1,
             const float* __restrict__ ggamma,const float* __restrict__ gbeta,
             const float* __restrict__ gWfc, const float* __restrict__ gbfc,
             float* __restrict__ out) {
    __shared__ Smem sm;
    const int tid    = threadIdx.x;
    const int bstart = blockIdx.x * G;

    // ---- one-time SMEM setup ----
    for (int i = tid; i < G * U; i += NTHR) {
        (&sm.h0[0][0])[i] = 0.0f; (&sm.c0[0][0])[i] = 0.0f;
        (&sm.h1[0][0])[i] = 0.0f; (&sm.c1[0][0])[i] = 0.0f;
    }
    for (int i = tid; i < NF * ZD; i += NTHR) (&sm.Wx0[0][0])[i] = gWx0[i];
    for (int i = tid; i < ZD; i += NTHR) { sm.b0[i] = gb0[i]; sm.b1[i] = gb1[i]; }
    for (int i = tid; i < U;  i += NTHR) {
        sm.tau0[i] = gtau0[i]; sm.s0[i] = gs0[i];
        sm.tau1[i] = gtau1[i]; sm.s1[i] = gs1[i];
        sm.gm[i]   = ggamma[i]; sm.bt[i] = gbeta[i];
    }
    for (int i = tid; i < U * NC; i += NTHR) sm.Wfc[i] = gWfc[i];
    if (tid < NC) sm.bfc[tid] = gbfc[tid];
    if (tid < G)  sm.tm[0][tid] = times[(size_t)(bstart + tid) * TT];
    if (tid < G * NF) {
        int g = tid / NF, f = tid - g * NF;
        sm.x[0][g][f] = inputs[((size_t)(bstart + g) * TT) * NF + f];
    }
    __syncthreads();

    const int ks   = tid >> 7;          // K-slab (0/1)
    const int col  = (tid & 127) * 4;   // 4 output columns of 512
    const int gg   = tid >> 7;          // gate-phase batch (items gg and gg+2)
    const int uu   = tid & 127;
    const int lane = tid & 31;
    const int wsub = (tid >> 5) & 3;

    for (int t = 0; t < TT; ++t) {
        const int buf = t & 1;

        // ================= layer 0: z = x@Wx0 + h0@Wh0 + b0 =================
        unsigned long long acc[G][2];
        if (ks == 0) {
            #pragma unroll
            for (int g = 0; g < G; ++g) {
                float xa = sm.x[buf][g][0], xb = sm.x[buf][g][1], xc = sm.x[buf][g][2];
                float a[4];
                #pragma unroll
                for (int j = 0; j < 4; ++j)
                    a[j] = sm.b0[col + j] + xa * sm.Wx0[0][col + j]
                                          + xb * sm.Wx0[1][col + j]
                                          + xc * sm.Wx0[2][col + j];
                acc[g][0] = pack2(a[0], a[1]);
                acc[g][1] = pack2(a[2], a[3]);
            }
        } else {
            #pragma unroll
            for (int g = 0; g < G; ++g) { acc[g][0] = 0ull; acc[g][1] = 0ull; }
        }
        mv_accum(gWh0, &sm.h0[0][0], ks, col, acc);
        #pragma unroll
        for (int g = 0; g < G; ++g) {
            float2 p = unpack2(acc[g][0]), q = unpack2(acc[g][1]);
            *reinterpret_cast<float4*>(&sm.z[ks][g][col]) = make_float4(p.x, p.y, q.x, q.y);
        }
        __syncthreads();

        // ---- gates layer 0 (+ LayerNorm statistics) ----
        float hA = sm.h0[gg][uu],     cA = sm.c0[gg][uu];
        float hB = sm.h0[gg + 2][uu], cB = sm.c0[gg + 2][uu];
        plstm_gate(&sm.z[0][gg][0],     &sm.z[1][gg][0],     uu, sm.tm[buf][gg],
                   sm.tau0[uu], sm.s0[uu], hA, cA);
        plstm_gate(&sm.z[0][gg + 2][0], &sm.z[1][gg + 2][0], uu, sm.tm[buf][gg + 2],
                   sm.tau0[uu], sm.s0[uu], hB, cB);
        sm.h0[gg][uu] = hA;     sm.c0[gg][uu] = cA;
        sm.h0[gg + 2][uu] = hB; sm.c0[gg + 2][uu] = cB;

        float sA = hA, qA = hA * hA, sB = hB, qB = hB * hB;
        #pragma unroll
        for (int o = 16; o; o >>= 1) {
            sA += __shfl_xor_sync(0xffffffffu, sA, o);
            qA += __shfl_xor_sync(0xffffffffu, qA, o);
            sB += __shfl_xor_sync(0xffffffffu, sB, o);
            qB += __shfl_xor_sync(0xffffffffu, qB, o);
        }
        if (lane == 0) {
            sm.red_s[gg][wsub] = sA;     sm.red_q[gg][wsub] = qA;
            sm.red_s[gg + 2][wsub] = sB; sm.red_q[gg + 2][wsub] = qB;
        }
        __syncthreads();
        if (tid < G) {
            float s4 = sm.red_s[tid][0] + sm.red_s[tid][1] + sm.red_s[tid][2] + sm.red_s[tid][3];
            float q4 = sm.red_q[tid][0] + sm.red_q[tid][1] + sm.red_q[tid][2] + sm.red_q[tid][3];
            float mu  = s4 * (1.0f / U);
            float var = fmaxf(q4 * (1.0f / U) - mu * mu, 0.0f);
            sm.mu[tid] = mu;
            sm.rs[tid] = rsqrtf(var + LN_EPS_);
        }
        __syncthreads();
        sm.hn[gg][uu]     = sm.gm[uu] * (hA - sm.mu[gg])     * sm.rs[gg]     + sm.bt[uu];
        sm.hn[gg + 2][uu] = sm.gm[uu] * (hB - sm.mu[gg + 2]) * sm.rs[gg + 2] + sm.bt[uu];
        __syncthreads();

        // ---- prefetch next step's x/t into the other buffer ----
        if (t + 1 < TT) {
            int nb = buf ^ 1;
            if (tid < G) sm.tm[nb][tid] = times[(size_t)(bstart + tid) * TT + (t + 1)];
            if (tid < G * NF) {
                int g = tid / NF, f = tid - g * NF;
                sm.x[nb][g][f] = inputs[((size_t)(bstart + g) * TT + (t + 1)) * NF + f];
            }
        }

        // ================= layer 1: z = hn@Wx1 + h1@Wh1 + b1 =================
        if (ks == 0) {
            #pragma unroll
            for (int g = 0; g < G; ++g) {
                acc[g][0] = pack2(sm.b1[col + 0], sm.b1[col + 1]);
                acc[g][1] = pack2(sm.b1[col + 2], sm.b1[col + 3]);
            }
        } else {
            #pragma unroll
            for (int g = 0; g < G; ++g) { acc[g][0] = 0ull; acc[g][1] = 0ull; }
        }
        mv_accum(gWx1, &sm.hn[0][0], ks, col, acc);
        mv_accum(gWh1, &sm.h1[0][0], ks, col, acc);
        #pragma unroll
        for (int g = 0; g < G; ++g) {
            float2 p = unpack2(acc[g][0]), q = unpack2(acc[g][1]);
            *reinterpret_cast<float4*>(&sm.z[ks][g][col]) = make_float4(p.x, p.y, q.x, q.y);
        }
        __syncthreads();

        // ---- gates layer 1 ----
        float h1A = sm.h1[gg][uu],     c1A = sm.c1[gg][uu];
        float h1B = sm.h1[gg + 2][uu], c1B = sm.c1[gg + 2][uu];
        plstm_gate(&sm.z[0][gg][0],     &sm.z[1][gg][0],     uu, sm.tm[buf][gg],
                   sm.tau1[uu], sm.s1[uu], h1A, c1A);
        plstm_gate(&sm.z[0][gg + 2][0], &sm.z[1][gg + 2][0], uu, sm.tm[buf][gg + 2],
                   sm.tau1[uu], sm.s1[uu], h1B, c1B);
        sm.h1[gg][uu] = h1A;     sm.c1[gg][uu] = c1A;
        sm.h1[gg + 2][uu] = h1B; sm.c1[gg + 2][uu] = c1B;
        __syncthreads();

        // ================= output: softmax(h1 @ Wfc + bfc) =================
        if (tid < 160) {                       // 40 (g,c) pairs x 4 threads
            int pair = tid >> 2, sub = tid & 3;
            int g = pair / NC, c = pair - g * NC;
            float a = 0.0f;
            #pragma unroll
            for (int i = 0; i < 32; ++i) {
                int u = sub + 4 * i;
                a += sm.h1[g][u] * sm.Wfc[u * NC + c];
            }
            a += __shfl_xor_sync(0xffffffffu, a, 1);
            a += __shfl_xor_sync(0xffffffffu, a, 2);
            if (sub == 0) sm.logits[g][c] = a + sm.bfc[c];
        }
        __syncthreads();
        if (tid < G) {
            float mx = -1e30f;
            #pragma unroll
            for (int c = 0; c < NC; ++c) mx = fmaxf(mx, sm.logits[tid][c]);
            float e[NC]; float s = 0.0f;
            #pragma unroll
            for (int c = 0; c < NC; ++c) { e[c] = expf(sm.logits[tid][c] - mx); s += e[c]; }
            float inv = 1.0f / s;
            float* op = out + ((size_t)(bstart + tid) * TT + t) * NC;
            #pragma unroll
            for (int c = 0; c < NC; ++c) op[c] = e[c] * inv;
        }
        // No trailing barrier needed: every SMEM buffer written early in the next
        // iteration is separated from this iteration's readers by >=1 __syncthreads().
    }
}

extern "C" void kernel_launch(void* const* d_in, const int* in_sizes, int n_in,
                              void* d_out, int out_size) {
    const float* inputs = (const float*)d_in[0];
    const float* times  = (const float*)d_in[1];
    const float* Wx0    = (const float*)d_in[2];
    const float* Wh0    = (const float*)d_in[3];
    const float* b0     = (const float*)d_in[4];
    const float* tau0   = (const float*)d_in[5];
    const float* s0     = (const float*)d_in[6];
    const float* Wx1    = (const float*)d_in[7];
    const float* Wh1    = (const float*)d_in[8];
    const float* b1     = (const float*)d_in[9];
    const float* tau1   = (const float*)d_in[10];
    const float* s1     = (const float*)d_in[11];
    const float* gamma  = (const float*)d_in[12];
    const float* beta   = (const float*)d_in[13];
    const float* Wfc    = (const float*)d_in[14];
    const float* bfc    = (const float*)d_in[15];

    plstm_kernel<<<NBLK, NTHR>>>(inputs, times, Wx0, Wh0, b0, tau0, s0,
                                 Wx1, Wh1, b1, tau1, s1, gamma, beta,
                                 Wfc, bfc, (float*)d_out);
}

// round 3
// speedup vs baseline: 1.0066x; 1.0066x over previous
#include <cuda_runtime.h>
#include <math.h>

// Problem constants (fixed by setup_inputs)
#define U      128     // hidden units
#define ZD     512     // 4*U gate width
#define NC     10      // classes
#define NF     3       // input features
#define TT     1000    // timesteps
#define BB     256     // batch
#define G      4       // batch elements per block
#define NBLK   (BB/G)  // 64 blocks
#define NTHR   256

#define R_ON_   0.05f
#define ALPHA_  0.001f
#define LN_EPS_ 1e-3f

// ---- packed f32x2 helpers (Blackwell FFMA2: 2x fp32 FMA throughput) ----
__device__ __forceinline__ unsigned long long pack2(float a, float b) {
    unsigned long long r;
    asm("mov.b64 %0, {%1, %2};" : "=l"(r) : "f"(a), "f"(b));
    return r;
}
__device__ __forceinline__ float2 unpack2(unsigned long long v) {
    float2 r;
    asm("mov.b64 {%0, %1}, %2;" : "=f"(r.x), "=f"(r.y) : "l"(v));
    return r;
}
__device__ __forceinline__ void fma2p(unsigned long long& acc,
                                      unsigned long long w,
                                      unsigned long long h) {
    asm("fma.rn.f32x2 %0, %1, %2, %0;" : "+l"(acc) : "l"(w), "l"(h));
}

__device__ __forceinline__ float sigmoidf_(float x) { return 1.0f / (1.0f + expf(-x)); }

struct __align__(16) Smem {
    float z[2][G][ZD];          // per-K-slab partial gate pre-activations
    float h0[G][U], c0[G][U];
    float h1[G][U], c1[G][U];
    float hn[G][U];             // layernormed h0
    float Wx0[NF][ZD];
    float b0[ZD], b1[ZD];
    float tau0[U], s0[U], tau1[U], s1[U], gm[U], bt[U];
    float Wfc[U * NC];
    float bfc[NC];
    float x[2][G][NF];          // double-buffered inputs
    float tm[2][G];             // double-buffered times
    float red_s[G][4], red_q[G][4];
    float mu[G], rs[G];
    float logits[G][NC];
};

// Accumulate one 64-row K-slab of  hin[G][U] @ W[U][ZD]  into acc (4 cols/thread).
__device__ __forceinline__ void mv_accum(const float* __restrict__ W,
                                         const float* __restrict__ hin,
                                         int ks, int col,
                                         unsigned long long acc[G][2]) {
    const int kbase = ks * 64;
    #pragma unroll 4
    for (int k = 0; k < 64; ++k) {
        const int kk = kbase + k;
        float4 w = *reinterpret_cast<const float4*>(W + (size_t)kk * ZD + col);
        unsigned long long w01 = pack2(w.x, w.y);
        unsigned long long w23 = pack2(w.z, w.w);
        #pragma unroll
        for (int g = 0; g < G; ++g) {
            float hv = hin[g * U + kk];
            unsigned long long h2 = pack2(hv, hv);
            fma2p(acc[g][0], w01, h2);
            fma2p(acc[g][1], w23, h2);
        }
    }
}

// PhasedLSTM gate + time-gate update for one (batch, unit).
__device__ __forceinline__ void plstm_gate(const float* __restrict__ z0,
                                           const float* __restrict__ z1,
                                           int u, float tcur, float tau, float s,
                                           float& h, float& c) {
    float zi = z0[u]         + z1[u];
    float zf = z0[u + 128]   + z1[u + 128];
    float zg = z0[u + 256]   + z1[u + 256];
    float zo = z0[u + 384]   + z1[u + 384];
    float ch = sigmoidf_(zf) * c + sigmoidf_(zi) * tanhf(zg);
    float hh = sigmoidf_(zo) * tanhf(ch);

    float d = tcur - s;
    float m = fmodf(d, tau);          // exact, matches lax.rem
    if (m < 0.0f) m += tau;           // python-style mod (sign of divisor)
    float phi = m / tau;
    float kgate;
    if (phi < 0.5f * R_ON_)      kgate = 2.0f * phi / R_ON_;
    else if (phi < R_ON_)        kgate = 2.0f - 2.0f * phi / R_ON_;
    else                         kgate = ALPHA_ * phi;

    h = kgate * hh + (1.0f - kgate) * h;
    c = kgate * ch + (1.0f - kgate) * c;
}

__global__ void __launch_bounds__(NTHR, 1)
plstm_kernel(const float* __restrict__ inputs, const float* __restrict__ times,
             const float* __restrict__ gWx0, const float* __restrict__ gWh0,
             const float* __restrict__ gb0,  const float* __restrict__ gtau0,
             const float* __restrict__ gs0,  const float* __restrict__ gWx1,
             const float* __restrict__ gWh1, const float* __restrict__ gb1,
             const float* __restrict__ gtau1,const float* __restrict__ gs1,
             const float* __restrict__ ggamma,const float* __restrict__ gbeta,
             const float* __restrict__ gWfc, const float* __restrict__ gbfc,
             float* __restrict__ out) {
    __shared__ Smem sm;
    const int tid    = threadIdx.x;
    const int bstart = blockIdx.x * G;

    // ---- one-time SMEM setup ----
    for (int i = tid; i < G * U; i += NTHR) {
        (&sm.h0[0][0])[i] = 0.0f; (&sm.c0[0][0])[i] = 0.0f;
        (&sm.h1[0][0])[i] = 0.0f; (&sm.c1[0][0])[i] = 0.0f;
    }
    for (int i = tid; i < NF * ZD; i += NTHR) (&sm.Wx0[0][0])[i] = gWx0[i];
    for (int i = tid; i < ZD; i += NTHR) { sm.b0[i] = gb0[i]; sm.b1[i] = gb1[i]; }
    for (int i = tid; i < U;  i += NTHR) {
        sm.tau0[i] = gtau0[i]; sm.s0[i] = gs0[i];
        sm.tau1[i] = gtau1[i]; sm.s1[i] = gs1[i];
        sm.gm[i]   = ggamma[i]; sm.bt[i] = gbeta[i];
    }
    for (int i = tid; i < U * NC; i += NTHR) sm.Wfc[i] = gWfc[i];
    if (tid < NC) sm.bfc[tid] = gbfc[tid];
    if (tid < G)  sm.tm[0][tid] = times[(size_t)(bstart + tid) * TT];
    if (tid < G * NF) {
        int g = tid / NF, f = tid - g * NF;
        sm.x[0][g][f] = inputs[((size_t)(bstart + g) * TT) * NF + f];
    }
    __syncthreads();

    const int ks   = tid >> 7;          // K-slab (0/1)
    const int col  = (tid & 127) * 4;   // 4 output columns of 512
    const int gg   = tid >> 7;          // gate-phase batch (items gg and gg+2)
    const int uu   = tid & 127;
    const int lane = tid & 31;
    const int wsub = (tid >> 5) & 3;

    for (int t = 0; t < TT; ++t) {
        const int buf = t & 1;

        // ================= layer 0: z = x@Wx0 + h0@Wh0 + b0 =================
        unsigned long long acc[G][2];
        if (ks == 0) {
            #pragma unroll
            for (int g = 0; g < G; ++g) {
                float xa = sm.x[buf][g][0], xb = sm.x[buf][g][1], xc = sm.x[buf][g][2];
                float a[4];
                #pragma unroll
                for (int j = 0; j < 4; ++j)
                    a[j] = sm.b0[col + j] + xa * sm.Wx0[0][col + j]
                                          + xb * sm.Wx0[1][col + j]
                                          + xc * sm.Wx0[2][col + j];
                acc[g][0] = pack2(a[0], a[1]);
                acc[g][1] = pack2(a[2], a[3]);
            }
        } else {
            #pragma unroll
            for (int g = 0; g < G; ++g) { acc[g][0] = 0ull; acc[g][1] = 0ull; }
        }
        mv_accum(gWh0, &sm.h0[0][0], ks, col, acc);
        #pragma unroll
        for (int g = 0; g < G; ++g) {
            float2 p = unpack2(acc[g][0]), q = unpack2(acc[g][1]);
            *reinterpret_cast<float4*>(&sm.z[ks][g][col]) = make_float4(p.x, p.y, q.x, q.y);
        }
        __syncthreads();

        // ---- gates layer 0 (+ LayerNorm statistics) ----
        float hA = sm.h0[gg][uu],     cA = sm.c0[gg][uu];
        float hB = sm.h0[gg + 2][uu], cB = sm.c0[gg + 2][uu];
        plstm_gate(&sm.z[0][gg][0],     &sm.z[1][gg][0],     uu, sm.tm[buf][gg],
                   sm.tau0[uu], sm.s0[uu], hA, cA);
        plstm_gate(&sm.z[0][gg + 2][0], &sm.z[1][gg + 2][0], uu, sm.tm[buf][gg + 2],
                   sm.tau0[uu], sm.s0[uu], hB, cB);
        sm.h0[gg][uu] = hA;     sm.c0[gg][uu] = cA;
        sm.h0[gg + 2][uu] = hB; sm.c0[gg + 2][uu] = cB;

        float sA = hA, qA = hA * hA, sB = hB, qB = hB * hB;
        #pragma unroll
        for (int o = 16; o; o >>= 1) {
            sA += __shfl_xor_sync(0xffffffffu, sA, o);
            qA += __shfl_xor_sync(0xffffffffu, qA, o);
            sB += __shfl_xor_sync(0xffffffffu, sB, o);
            qB += __shfl_xor_sync(0xffffffffu, qB, o);
        }
        if (lane == 0) {
            sm.red_s[gg][wsub] = sA;     sm.red_q[gg][wsub] = qA;
            sm.red_s[gg + 2][wsub] = sB; sm.red_q[gg + 2][wsub] = qB;
        }
        __syncthreads();
        if (tid < G) {
            float s4 = sm.red_s[tid][0] + sm.red_s[tid][1] + sm.red_s[tid][2] + sm.red_s[tid][3];
            float q4 = sm.red_q[tid][0] + sm.red_q[tid][1] + sm.red_q[tid][2] + sm.red_q[tid][3];
            float mu  = s4 * (1.0f / U);
            float var = fmaxf(q4 * (1.0f / U) - mu * mu, 0.0f);
            sm.mu[tid] = mu;
            sm.rs[tid] = rsqrtf(var + LN_EPS_);
        }
        __syncthreads();
        sm.hn[gg][uu]     = sm.gm[uu] * (hA - sm.mu[gg])     * sm.rs[gg]     + sm.bt[uu];
        sm.hn[gg + 2][uu] = sm.gm[uu] * (hB - sm.mu[gg + 2]) * sm.rs[gg + 2] + sm.bt[uu];
        __syncthreads();

        // ---- prefetch next step's x/t into the other buffer ----
        if (t + 1 < TT) {
            int nb = buf ^ 1;
            if (tid < G) sm.tm[nb][tid] = times[(size_t)(bstart + tid) * TT + (t + 1)];
            if (tid < G * NF) {
                int g = tid / NF, f = tid - g * NF;
                sm.x[nb][g][f] = inputs[((size_t)(bstart + g) * TT + (t + 1)) * NF + f];
            }
        }

        // ================= layer 1: z = hn@Wx1 + h1@Wh1 + b1 =================
        if (ks == 0) {
            #pragma unroll
            for (int g = 0; g < G; ++g) {
                acc[g][0] = pack2(sm.b1[col + 0], sm.b1[col + 1]);
                acc[g][1] = pack2(sm.b1[col + 2], sm.b1[col + 3]);
            }
        } else {
            #pragma unroll
            for (int g = 0; g < G; ++g) { acc[g][0] = 0ull; acc[g][1] = 0ull; }
        }
        mv_accum(gWx1, &sm.hn[0][0], ks, col, acc);
        mv_accum(gWh1, &sm.h1[0][0], ks, col, acc);
        #pragma unroll
        for (int g = 0; g < G; ++g) {
            float2 p = unpack2(acc[g][0]), q = unpack2(acc[g][1]);
            *reinterpret_cast<float4*>(&sm.z[ks][g][col]) = make_float4(p.x, p.y, q.x, q.y);
        }
        __syncthreads();

        // ---- gates layer 1 ----
        float h1A = sm.h1[gg][uu],     c1A = sm.c1[gg][uu];
        float h1B = sm.h1[gg + 2][uu], c1B = sm.c1[gg + 2][uu];
        plstm_gate(&sm.z[0][gg][0],     &sm.z[1][gg][0],     uu, sm.tm[buf][gg],
                   sm.tau1[uu], sm.s1[uu], h1A, c1A);
        plstm_gate(&sm.z[0][gg + 2][0], &sm.z[1][gg + 2][0], uu, sm.tm[buf][gg + 2],
                   sm.tau1[uu], sm.s1[uu], h1B, c1B);
        sm.h1[gg][uu] = h1A;     sm.c1[gg][uu] = c1A;
        sm.h1[gg + 2][uu] = h1B; sm.c1[gg + 2][uu] = c1B;
        __syncthreads();

        // ================= output: softmax(h1 @ Wfc + bfc) =================
        if (tid < 160) {                       // 40 (g,c) pairs x 4 threads
            int pair = tid >> 2, sub = tid & 3;
            int g = pair / NC, c = pair - g * NC;
            float a = 0.0f;
            #pragma unroll
            for (int i = 0; i < 32; ++i) {
                int u = sub + 4 * i;
                a += sm.h1[g][u] * sm.Wfc[u * NC + c];
            }
            a += __shfl_xor_sync(0xffffffffu, a, 1);
            a += __shfl_xor_sync(0xffffffffu, a, 2);
            if (sub == 0) sm.logits[g][c] = a + sm.bfc[c];
        }
        __syncthreads();
        if (tid < G) {
            float mx = -1e30f;
            #pragma unroll
            for (int c = 0; c < NC; ++c) mx = fmaxf(mx, sm.logits[tid][c]);
            float e[NC]; float s = 0.0f;
            #pragma unroll
            for (int c = 0; c < NC; ++c) { e[c] = expf(sm.logits[tid][c] - mx); s += e[c]; }
            float inv = 1.0f / s;
            float* op = out + ((size_t)(bstart + tid) * TT + t) * NC;
            #pragma unroll
            for (int c = 0; c < NC; ++c) op[c] = e[c] * inv;
        }
        // No trailing barrier needed: every SMEM buffer written early in the next
        // iteration is separated from this iteration's readers by >=1 __syncthreads().
    }
}

extern "C" void kernel_launch(void* const* d_in, const int* in_sizes, int n_in,
                              void* d_out, int out_size) {
    const float* inputs = (const float*)d_in[0];
    const float* times  = (const float*)d_in[1];
    const float* Wx0    = (const float*)d_in[2];
    const float* Wh0    = (const float*)d_in[3];
    const float* b0     = (const float*)d_in[4];
    const float* tau0   = (const float*)d_in[5];
    const float* s0     = (const float*)d_in[6];
    const float* Wx1    = (const float*)d_in[7];
    const float* Wh1    = (const float*)d_in[8];
    const float* b1     = (const float*)d_in[9];
    const float* tau1   = (const float*)d_in[10];
    const float* s1     = (const float*)d_in[11];
    const float* gamma  = (const float*)d_in[12];
    const float* beta   = (const float*)d_in[13];
    const float* Wfc    = (const float*)d_in[14];
    const float* bfc    = (const float*)d_in[15];

    plstm_kernel<<<NBLK, NTHR>>>(inputs, times, Wx0, Wh0, b0, tau0, s0,
                                 Wx1, Wh1, b1, tau1, s1, gamma, beta,
                                 Wfc, bfc, (float*)d_out);
}